// round 10
// baseline (speedup 1.0000x reference)
#include <cuda_runtime.h>
#include <cuda_fp16.h>
#include <cuda_bf16.h>

#define NN 200000
#define EE 6400000
// R=3, B=5, H=16, C=8

// ---------------- scratch ----------------------------------------------------
__device__ float4  g_x4    [NN];          // (x0, x1, x2, 1.0) per node
__device__ float4  g_sx    [3 * NN];      // per (r,dst): sum x + count in .w
__device__ uint4   g_xw2h  [3 * NN];      // [r][n][8] layer2 messages, fp16 (16B)
__device__ uint4   g_sums2h[3 * NN];      // per (r,dst) sums, layer2, fp16 (16B)
__device__ float4  g_rootx2[NN * 2];      // h@root2 + bias2
__device__ float   g_cpack [728];         // staging: f32 weights
__device__ __half2 g_cph   [260];         // staging: half2 W2|root2|bias2

// ---------------- constant weights -------------------------------------------
// f32 bank: W1[144] | W2[384](unused) | root1[48] | bias1[16] | root2[128] | bias2[8]
__constant__ float c_pack[728];
#define CW1(i) c_pack[(i)]
#define CR1(i) c_pack[528 + (i)]
#define CB1(i) c_pack[576 + (i)]
// half2 bank: W2h[192] (r*64+k*4+q) | R2h[64] (k*4+q) | B2h[4]
__constant__ __half2 c_ph[260];
#define CW2H(i) c_ph[(i)]
#define CR2H(i) c_ph[192 + (i)]
#define CB2H(i) c_ph[256 + (i)]

// ---------------- vectorized global reductions -------------------------------
__device__ __forceinline__ void red_add_v4(float4* addr, float4 v) {
    asm volatile("red.relaxed.gpu.global.add.v4.f32 [%0], {%1,%2,%3,%4};"
                 :: "l"(addr), "f"(v.x), "f"(v.y), "f"(v.z), "f"(v.w) : "memory");
}
__device__ __forceinline__ void red_add_v4h2(uint4* addr, uint4 v) {
    asm volatile("red.relaxed.gpu.global.add.noftz.v4.f16x2 [%0], {%1,%2,%3,%4};"
                 :: "l"(addr), "r"(v.x), "r"(v.y), "r"(v.z), "r"(v.w) : "memory");
}

// ---------------- kernels ----------------------------------------------------

// Fused prep: pack x, zero g_sx, build f32 + half2 weight packs (block 0).
__global__ void prep1(const float* __restrict__ x,
                      const float* __restrict__ b1, const float* __restrict__ c1,
                      const float* __restrict__ b2, const float* __restrict__ c2,
                      const float* __restrict__ r1, const float* __restrict__ bs1,
                      const float* __restrict__ r2, const float* __restrict__ bs2) {
    int n = blockIdx.x * blockDim.x + threadIdx.x;
    if (n < NN) {
        g_x4[n] = make_float4(x[n * 3 + 0], x[n * 3 + 1], x[n * 3 + 2], 1.0f);
        float4 z = make_float4(0.f, 0.f, 0.f, 0.f);
        g_sx[n] = z;
        g_sx[NN + n] = z;
        g_sx[2 * NN + n] = z;
    }
    if (blockIdx.x == 0) {
        for (int t = threadIdx.x; t < 144; t += blockDim.x) {  // W1: [r][i][o]
            int r = t / 48, rem = t % 48, i = rem / 16, o = rem % 16;
            float acc = 0.f;
            #pragma unroll
            for (int b = 0; b < 5; b++) acc += c1[r * 5 + b] * b1[(b * 3 + i) * 16 + o];
            g_cpack[t] = acc;
        }
        for (int t = threadIdx.x; t < 48; t += blockDim.x)  g_cpack[528 + t] = r1[t];
        for (int t = threadIdx.x; t < 16; t += blockDim.x)  g_cpack[576 + t] = bs1[t];
        // half2 W2: [r][k][q] pairs over output-channel c = 2q, 2q+1
        for (int t = threadIdx.x; t < 192; t += blockDim.x) {
            int r = t / 64, rem = t % 64, k = rem / 4, q = rem % 4;
            float a0 = 0.f, a1 = 0.f;
            #pragma unroll
            for (int b = 0; b < 5; b++) {
                float cc = c2[r * 5 + b];
                a0 += cc * b2[(b * 16 + k) * 8 + 2 * q];
                a1 += cc * b2[(b * 16 + k) * 8 + 2 * q + 1];
            }
            g_cph[t] = __floats2half2_rn(a0, a1);
        }
        for (int t = threadIdx.x; t < 64; t += blockDim.x) {  // root2 half2
            int k = t / 4, q = t % 4;
            g_cph[192 + t] = __floats2half2_rn(r2[k * 8 + 2 * q], r2[k * 8 + 2 * q + 1]);
        }
        for (int t = threadIdx.x; t < 4; t += blockDim.x)     // bias2 half2
            g_cph[256 + t] = __floats2half2_rn(bs2[2 * t], bs2[2 * t + 1]);
    }
}

// Zero the fp16 layer-2 accumulator (side stream, hidden under scatter1).
__global__ void zero2h() {
    int i = blockIdx.x * blockDim.x + threadIdx.x;
    if (i < 3 * NN) g_sums2h[i] = make_uint4(0u, 0u, 0u, 0u);
}

// Layer-1 edge scatter: 4 edges/thread, int4 index loads.
__global__ void scatter1(const int4* __restrict__ src4, const int4* __restrict__ dst4,
                         const int4* __restrict__ et4) {
    int t = blockIdx.x * blockDim.x + threadIdx.x;
    if (t >= EE / 4) return;
    int4 s = src4[t], d = dst4[t], r = et4[t];
    float4 v0 = __ldg(&g_x4[s.x]);
    float4 v1 = __ldg(&g_x4[s.y]);
    float4 v2 = __ldg(&g_x4[s.z]);
    float4 v3 = __ldg(&g_x4[s.w]);
    red_add_v4(&g_sx[r.x * NN + d.x], v0);
    red_add_v4(&g_sx[r.y * NN + d.y], v1);
    red_add_v4(&g_sx[r.z * NN + d.z], v2);
    red_add_v4(&g_sx[r.w * NN + d.w], v3);
}

// Fused: layer-1 finalize (f32) + layer-2 dense (HFMA2).
__global__ void fin1dense2() {
    int n = blockIdx.x * blockDim.x + threadIdx.x;
    if (n >= NN) return;
    float h[16];
    #pragma unroll
    for (int o = 0; o < 16; o++) h[o] = CB1(o);
    float4 xv = g_x4[n];
    float xi[3] = {xv.x, xv.y, xv.z};
    #pragma unroll
    for (int i = 0; i < 3; i++)
        #pragma unroll
        for (int o = 0; o < 16; o++) h[o] += xi[i] * CR1(i * 16 + o);
    #pragma unroll
    for (int r = 0; r < 3; r++) {
        float4 s = g_sx[r * NN + n];
        float inv = 1.0f / fmaxf(s.w, 1.0f);
        float m[3] = {s.x * inv, s.y * inv, s.z * inv};
        #pragma unroll
        for (int i = 0; i < 3; i++)
            #pragma unroll
            for (int o = 0; o < 16; o++) h[o] += m[i] * CW1(r * 48 + i * 16 + o);
    }
    // relu + broadcast to half2
    __half2 hh[16];
    #pragma unroll
    for (int o = 0; o < 16; o++) {
        float v = fmaxf(h[o], 0.f);
        hh[o] = __float2half2_rn(v);
    }
    // Layer-2 messages: 3 relations x 4 half2-accumulators (HFMA2).
    #pragma unroll
    for (int r = 0; r < 3; r++) {
        __half2 a0 = __float2half2_rn(0.f), a1 = a0, a2 = a0, a3 = a0;
        #pragma unroll
        for (int k = 0; k < 16; k++) {
            a0 = __hfma2(hh[k], CW2H(r * 64 + k * 4 + 0), a0);
            a1 = __hfma2(hh[k], CW2H(r * 64 + k * 4 + 1), a1);
            a2 = __hfma2(hh[k], CW2H(r * 64 + k * 4 + 2), a2);
            a3 = __hfma2(hh[k], CW2H(r * 64 + k * 4 + 3), a3);
        }
        uint4 packed;
        packed.x = *reinterpret_cast<unsigned*>(&a0);
        packed.y = *reinterpret_cast<unsigned*>(&a1);
        packed.z = *reinterpret_cast<unsigned*>(&a2);
        packed.w = *reinterpret_cast<unsigned*>(&a3);
        g_xw2h[r * NN + n] = packed;
    }
    // Root path (HFMA2, stored back as f32 for finalize2).
    __half2 b0 = CB2H(0), b1 = CB2H(1), b2 = CB2H(2), b3 = CB2H(3);
    #pragma unroll
    for (int k = 0; k < 16; k++) {
        b0 = __hfma2(hh[k], CR2H(k * 4 + 0), b0);
        b1 = __hfma2(hh[k], CR2H(k * 4 + 1), b1);
        b2 = __hfma2(hh[k], CR2H(k * 4 + 2), b2);
        b3 = __hfma2(hh[k], CR2H(k * 4 + 3), b3);
    }
    float2 f0 = __half22float2(b0), f1 = __half22float2(b1);
    float2 f2 = __half22float2(b2), f3 = __half22float2(b3);
    g_rootx2[n * 2 + 0] = make_float4(f0.x, f0.y, f1.x, f1.y);
    g_rootx2[n * 2 + 1] = make_float4(f2.x, f2.y, f3.x, f3.y);
}

// Layer-2 edge scatter: 4 edges/thread, 1 gather + 1 fp16 RED per edge.
__global__ void scatter2(const int4* __restrict__ src4, const int4* __restrict__ dst4,
                         const int4* __restrict__ et4) {
    int t = blockIdx.x * blockDim.x + threadIdx.x;
    if (t >= EE / 4) return;
    int4 s = src4[t], d = dst4[t], r = et4[t];
    uint4 p0 = __ldg(&g_xw2h[r.x * NN + s.x]);
    uint4 p1 = __ldg(&g_xw2h[r.y * NN + s.y]);
    uint4 p2 = __ldg(&g_xw2h[r.z * NN + s.z]);
    uint4 p3 = __ldg(&g_xw2h[r.w * NN + s.w]);
    red_add_v4h2(&g_sums2h[r.x * NN + d.x], p0);
    red_add_v4h2(&g_sums2h[r.y * NN + d.y], p1);
    red_add_v4h2(&g_sums2h[r.z * NN + d.z], p2);
    red_add_v4h2(&g_sums2h[r.w * NN + d.w], p3);
}

// Layer-2 finalize + log_softmax. One thread per node. Counts from g_sx.w.
__global__ void finalize2(float* __restrict__ out) {
    int n = blockIdx.x * blockDim.x + threadIdx.x;
    if (n >= NN) return;
    float v[8];
    {
        float4 a = g_rootx2[n * 2 + 0], b = g_rootx2[n * 2 + 1];
        v[0]=a.x; v[1]=a.y; v[2]=a.z; v[3]=a.w;
        v[4]=b.x; v[5]=b.y; v[6]=b.z; v[7]=b.w;
    }
    #pragma unroll
    for (int r = 0; r < 3; r++) {
        float inv = 1.0f / fmaxf(g_sx[r * NN + n].w, 1.0f);
        uint4 p = g_sums2h[r * NN + n];
        float2 f0 = __half22float2(*reinterpret_cast<__half2*>(&p.x));
        float2 f1 = __half22float2(*reinterpret_cast<__half2*>(&p.y));
        float2 f2 = __half22float2(*reinterpret_cast<__half2*>(&p.z));
        float2 f3 = __half22float2(*reinterpret_cast<__half2*>(&p.w));
        v[0] += f0.x*inv; v[1] += f0.y*inv; v[2] += f1.x*inv; v[3] += f1.y*inv;
        v[4] += f2.x*inv; v[5] += f2.y*inv; v[6] += f3.x*inv; v[7] += f3.y*inv;
    }
    float m = v[0];
    #pragma unroll
    for (int i = 1; i < 8; i++) m = fmaxf(m, v[i]);
    float s = 0.f;
    #pragma unroll
    for (int i = 0; i < 8; i++) s += expf(v[i] - m);
    float lse = m + logf(s);
    float4* o = (float4*)(out + (size_t)n * 8);
    o[0] = make_float4(v[0]-lse, v[1]-lse, v[2]-lse, v[3]-lse);
    o[1] = make_float4(v[4]-lse, v[5]-lse, v[6]-lse, v[7]-lse);
}

// ---------------- host -------------------------------------------------------
extern "C" void kernel_launch(void* const* d_in, const int* in_sizes, int n_in,
                              void* d_out, int out_size) {
    const float *x = nullptr, *b1 = nullptr, *c1 = nullptr, *r1 = nullptr, *bs1 = nullptr;
    const float *b2 = nullptr, *c2 = nullptr, *r2 = nullptr, *bs2 = nullptr;
    const int *ei = nullptr, *et = nullptr;
    for (int i = 0; i < n_in; i++) {
        switch (in_sizes[i]) {
            case NN * 3:      x   = (const float*)d_in[i]; break;
            case 2 * EE:      ei  = (const int*)d_in[i];   break;
            case EE:          et  = (const int*)d_in[i];   break;
            case 5 * 3 * 16:  b1  = (const float*)d_in[i]; break;
            case 3 * 16:      r1  = (const float*)d_in[i]; break;
            case 16:          bs1 = (const float*)d_in[i]; break;
            case 5 * 16 * 8:  b2  = (const float*)d_in[i]; break;
            case 16 * 8:      r2  = (const float*)d_in[i]; break;
            case 8:           bs2 = (const float*)d_in[i]; break;
            case 15:          if (!c1) c1 = (const float*)d_in[i];
                              else     c2 = (const float*)d_in[i]; break;
            default: break;
        }
    }
    const int4* src4 = (const int4*)ei;
    const int4* dst4 = (const int4*)(ei + EE);
    const int4* et4  = (const int4*)et;
    float* out = (float*)d_out;

    // Lazy resource creation (first call is uncaptured correctness run).
    static cudaStream_t s_side = nullptr;
    static cudaEvent_t  e_fork = nullptr, e_prep = nullptr, e_side = nullptr;
    static void *a_cpack = nullptr, *a_cph = nullptr;
    if (!s_side) {
        cudaStreamCreateWithFlags(&s_side, cudaStreamNonBlocking);
        cudaEventCreateWithFlags(&e_fork, cudaEventDisableTiming);
        cudaEventCreateWithFlags(&e_prep, cudaEventDisableTiming);
        cudaEventCreateWithFlags(&e_side, cudaEventDisableTiming);
        cudaGetSymbolAddress(&a_cpack, g_cpack);
        cudaGetSymbolAddress(&a_cph,   g_cph);
    }

    const int T = 256;

    // Fork side stream at launch start: zero the fp16 accumulator (9.6 MB),
    // hidden under prep1 + scatter1.
    cudaEventRecord(e_fork, 0);
    cudaStreamWaitEvent(s_side, e_fork, 0);
    zero2h<<<(3 * NN + T - 1) / T, T, 0, s_side>>>();

    prep1<<<(NN + T - 1) / T, T>>>(x, b1, c1, b2, c2, r1, bs1, r2, bs2);

    // Weight memcpys on side stream — hidden behind scatter1.
    cudaEventRecord(e_prep, 0);
    cudaStreamWaitEvent(s_side, e_prep, 0);
    cudaMemcpyToSymbolAsync(c_pack, a_cpack, 728 * sizeof(float), 0,
                            cudaMemcpyDeviceToDevice, s_side);
    cudaMemcpyToSymbolAsync(c_ph, a_cph, 260 * sizeof(__half2), 0,
                            cudaMemcpyDeviceToDevice, s_side);
    cudaEventRecord(e_side, s_side);

    scatter1<<<(EE / 4) / T, T>>>(src4, dst4, et4);

    // Join: fin1dense2 needs the constant banks; scatter2 needs zeroed sums.
    cudaStreamWaitEvent(0, e_side, 0);
    fin1dense2<<<(NN + T - 1) / T, T>>>();
    scatter2<<<(EE / 4) / T, T>>>(src4, dst4, et4);
    finalize2<<<(NN + T - 1) / T, T>>>(out);
    (void)out_size;
}